// round 16
// baseline (speedup 1.0000x reference)
#include <cuda_runtime.h>
#include <math.h>
#include <stdint.h>

#define T_SEQ 4096
#define C_MODEL 1024
#define NHEADS 16
#define DHEAD 64

// Scratch (allocation-free rule: __device__ globals)
__device__ float g_q[T_SEQ * C_MODEL];
__device__ float g_k[T_SEQ * C_MODEL];
__device__ float g_v[T_SEQ * C_MODEL];
__device__ float g_attn[T_SEQ * C_MODEL];
// tf32-rounded copies of inputs (pre-pass)
__device__ float g_xr[T_SEQ * C_MODEL];
__device__ float g_wqr[C_MODEL * C_MODEL];
__device__ float g_wkr[C_MODEL * C_MODEL];
__device__ float g_wvr[C_MODEL * C_MODEL];
__device__ float g_wor[C_MODEL * C_MODEL];

__device__ __forceinline__ uint32_t f2tf32(float x) {
  uint32_t r;
  asm("cvt.rna.tf32.f32 %0, %1;" : "=r"(r) : "f"(x));
  return r;
}

__device__ __forceinline__ void mma_tf32(float* d, const uint32_t* a,
                                         const uint32_t* b) {
  asm volatile(
      "mma.sync.aligned.m16n8k8.row.col.f32.tf32.tf32.f32 "
      "{%0,%1,%2,%3}, {%4,%5,%6,%7}, {%8,%9}, {%0,%1,%2,%3};\n"
      : "+f"(d[0]), "+f"(d[1]), "+f"(d[2]), "+f"(d[3])
      : "r"(a[0]), "r"(a[1]), "r"(a[2]), "r"(a[3]), "r"(b[0]), "r"(b[1]));
}

__device__ __forceinline__ void cp16(uint32_t smem_addr, const void* gptr) {
  asm volatile("cp.async.cg.shared.global [%0], [%1], 16;" ::"r"(smem_addr),
               "l"(gptr));
}
#define CP_COMMIT() asm volatile("cp.async.commit_group;")
#define CP_WAIT0() asm volatile("cp.async.wait_group 0;" ::: "memory")
#define CP_WAIT1() asm volatile("cp.async.wait_group 1;" ::: "memory")

// ---------------------------------------------------------------------------
// Pre-pass: RNA-round x and the four weight matrices to tf32 bit patterns.
// blockIdx.y selects tensor; values then flow raw through cp.async -> mma.
// ---------------------------------------------------------------------------
__global__ __launch_bounds__(256) void round_pass(
    const float* __restrict__ x, const float* __restrict__ wq,
    const float* __restrict__ wk, const float* __restrict__ wv,
    const float* __restrict__ wo, float* __restrict__ xr,
    float* __restrict__ wqr, float* __restrict__ wkr, float* __restrict__ wvr,
    float* __restrict__ wor) {
  const float* s;
  float* d;
  int n;
  switch (blockIdx.y) {
    case 0: s = x;  d = xr;  n = T_SEQ * C_MODEL;  break;
    case 1: s = wq; d = wqr; n = C_MODEL * C_MODEL; break;
    case 2: s = wk; d = wkr; n = C_MODEL * C_MODEL; break;
    case 3: s = wv; d = wvr; n = C_MODEL * C_MODEL; break;
    default: s = wo; d = wor; n = C_MODEL * C_MODEL; break;
  }
  const int idx = (blockIdx.x * 256 + threadIdx.x) * 4;
  if (idx < n) {
    float4 v = *(const float4*)(s + idx);
    v.x = __uint_as_float(f2tf32(v.x));
    v.y = __uint_as_float(f2tf32(v.y));
    v.z = __uint_as_float(f2tf32(v.z));
    v.w = __uint_as_float(f2tf32(v.w));
    *(float4*)(d + idx) = v;
  }
}

// ---------------------------------------------------------------------------
// tf32 GEMM, raw cp.async staging (inputs pre-rounded to tf32 bit patterns).
// C[M,N] = A[M,K] @ B[N,K]^T + bias[N].  CTA tile 128x128, BK=32.
// 4 warps (128 thr), warp tile 64x64 (2m x 2n): 32 LDS feed 32 MMAs per kk.
// Double-buffered smem, 2 CTAs/SM.
// ---------------------------------------------------------------------------
#define GP 36  // smem pitch (words): fragment bank = lane, 144B rows (16B ok)
#define GEMM_SMEM (2 * 2 * 128 * GP * 4)  // 73,728 B

template <bool ROUND>
__device__ __forceinline__ void gemm_body(
    const float* __restrict__ A, const float* __restrict__ B,
    const float* __restrict__ bias, float* __restrict__ Cout, int K, int bm,
    int bn) {
  extern __shared__ uint32_t gsm[];
  const uint32_t sbase = (uint32_t)__cvta_generic_to_shared(gsm);
  const int tid = threadIdx.x;
  const int lane = tid & 31;
  const int wid = tid >> 5;
  const int wm = wid >> 1;   // 0..1
  const int wn = wid & 1;    // 0..1
  const int l4 = lane >> 2;  // 0..7
  const int lm4 = lane & 3;  // 0..3

  // buffer b: A at gsm[b*2*128*GP], B at gsm[(b*2+1)*128*GP]
#define GSTAGE(kc, b)                                                         \
  do {                                                                        \
    const float* ag_ = A + (bm + tid) * K + (kc) * 32;                        \
    const float* bg_ = B + (bn + tid) * K + (kc) * 32;                        \
    const uint32_t as_ = sbase + ((b) * 2 * 128 * GP + tid * GP) * 4;         \
    const uint32_t bs_ = sbase + (((b) * 2 + 1) * 128 * GP + tid * GP) * 4;   \
    _Pragma("unroll") for (int ch_ = 0; ch_ < 8; ch_++) {                     \
      cp16(as_ + ch_ * 16, ag_ + ch_ * 4);                                    \
      cp16(bs_ + ch_ * 16, bg_ + ch_ * 4);                                    \
    }                                                                         \
    CP_COMMIT();                                                              \
  } while (0)

  float acc[4][8][4];
#pragma unroll
  for (int i = 0; i < 4; i++)
#pragma unroll
    for (int j = 0; j < 8; j++)
#pragma unroll
      for (int c = 0; c < 4; c++) acc[i][j][c] = 0.f;

  GSTAGE(0, 0);
  GSTAGE(1, 1);

  const int nk = K / 32;
  for (int c = 0; c < nk; c++) {
    const int b = c & 1;
    if (c < nk - 1) CP_WAIT1(); else CP_WAIT0();
    __syncthreads();

    const uint32_t* As = gsm + b * 2 * 128 * GP;
    const uint32_t* Bs = As + 128 * GP;
#pragma unroll
    for (int kk = 0; kk < 4; kk++) {
      uint32_t af[4][4], bf[8][2];
#pragma unroll
      for (int i = 0; i < 4; i++) {
        const int r = wm * 64 + i * 16 + l4;
        af[i][0] = As[r * GP + kk * 8 + lm4];
        af[i][1] = As[(r + 8) * GP + kk * 8 + lm4];
        af[i][2] = As[r * GP + kk * 8 + lm4 + 4];
        af[i][3] = As[(r + 8) * GP + kk * 8 + lm4 + 4];
      }
#pragma unroll
      for (int j = 0; j < 8; j++) {
        const int n = wn * 64 + j * 8 + l4;
        bf[j][0] = Bs[n * GP + kk * 8 + lm4];
        bf[j][1] = Bs[n * GP + kk * 8 + lm4 + 4];
      }
#pragma unroll
      for (int i = 0; i < 4; i++)
#pragma unroll
        for (int j = 0; j < 8; j++) mma_tf32(acc[i][j], af[i], bf[j]);
    }
    __syncthreads();
    if (c + 2 < nk) GSTAGE(c + 2, b);
  }

  // epilogue
#pragma unroll
  for (int j = 0; j < 8; j++) {
    const int cc = bn + wn * 64 + j * 8 + lm4 * 2;
    const float bi0 = bias[cc], bi1 = bias[cc + 1];
#pragma unroll
    for (int i = 0; i < 4; i++) {
      const int r = bm + wm * 64 + i * 16 + l4;
      float v00 = acc[i][j][0] + bi0, v01 = acc[i][j][1] + bi1;
      float v10 = acc[i][j][2] + bi0, v11 = acc[i][j][3] + bi1;
      if (ROUND) {
        v00 = __uint_as_float(f2tf32(v00));
        v01 = __uint_as_float(f2tf32(v01));
        v10 = __uint_as_float(f2tf32(v10));
        v11 = __uint_as_float(f2tf32(v11));
      }
      *(float2*)(Cout + r * C_MODEL + cc) = make_float2(v00, v01);
      *(float2*)(Cout + (r + 8) * C_MODEL + cc) = make_float2(v10, v11);
    }
  }
#undef GSTAGE
}

__global__ __launch_bounds__(128, 2) void gemm_qkv(
    const float* __restrict__ x, const float* __restrict__ Wq,
    const float* __restrict__ bq, float* __restrict__ q,
    const float* __restrict__ Wk, const float* __restrict__ bk,
    float* __restrict__ k, const float* __restrict__ Wv,
    const float* __restrict__ bv, float* __restrict__ v) {
  const float* B;
  const float* bias;
  float* out;
  if (blockIdx.z == 0) { B = Wq; bias = bq; out = q; }
  else if (blockIdx.z == 1) { B = Wk; bias = bk; out = k; }
  else { B = Wv; bias = bv; out = v; }
  gemm_body<true>(x, B, bias, out, C_MODEL, blockIdx.y * 128,
                  blockIdx.x * 128);
}

__global__ __launch_bounds__(128, 2) void gemm_out(
    const float* __restrict__ A, const float* __restrict__ B,
    const float* __restrict__ bias, float* __restrict__ Cout) {
  gemm_body<false>(A, B, bias, Cout, C_MODEL, blockIdx.y * 128,
                   blockIdx.x * 128);
}

// ---------------------------------------------------------------------------
// Causal flash attention, tf32 mma.sync, warp M-tile = 32 q-rows (R15 proven).
// Epilogue now rounds O to tf32 (so gemm_out can consume it raw) — same RNA
// rounding gemm_out's staging previously applied: bit-identical numerics.
// ---------------------------------------------------------------------------
#define KS_W 68
#define VS_W 76
#define SM_KS 0
#define SM_VS (2 * 64 * KS_W)
#define SM_PS (SM_VS + 2 * 64 * VS_W)
#define ATTN_WORDS (SM_PS + 128 * KS_W)
#define ATTN_SMEM (ATTN_WORDS * sizeof(uint32_t))  // 108,544 B

__global__ __launch_bounds__(128, 2) void flash_attn_tc(
    const float* __restrict__ Q, const float* __restrict__ K,
    const float* __restrict__ V, float* __restrict__ O) {
  extern __shared__ uint32_t smu[];
  const uint32_t sbase = (uint32_t)__cvta_generic_to_shared(smu);
  uint32_t* Ps = smu + SM_PS;  // [128][KS_W] (Q stage, then P tiles)

  const int qb = gridDim.x - 1 - blockIdx.x;  // heavy q-blocks first
  const int h  = blockIdx.y;
  const int tid = threadIdx.x;
  const int lane = tid & 31;
  const int w = tid >> 5;      // 0..3
  const int l4 = lane >> 2;    // 0..7
  const int lm4 = lane & 3;    // 0..3
  const float scale2 = 0.125f * 1.44269504088896f;  // 1/sqrt(64)*log2(e)
  const int nkt = 2 * qb + 2;
  const int wrow_last = qb * 128 + w * 32 + 31;

#define ASTAGE(t, b)                                                          \
  do {                                                                        \
    _Pragma("unroll") for (int i_ = 0; i_ < 8; i_++) {                        \
      const int c_ = tid + i_ * 128;                                          \
      const int row_ = c_ >> 4, col4_ = (c_ & 15) << 2;                       \
      cp16(sbase + (SM_KS + (b) * 64 * KS_W + row_ * KS_W + col4_) * 4,       \
           K + ((t) * 64 + row_) * C_MODEL + h * DHEAD + col4_);              \
      cp16(sbase + (SM_VS + (b) * 64 * VS_W + row_ * VS_W + col4_) * 4,       \
           V + ((t) * 64 + row_) * C_MODEL + h * DHEAD + col4_);              \
    }                                                                         \
    CP_COMMIT();                                                              \
  } while (0)

  ASTAGE(0, 0);

  // stage Q [128][64] into Ps: 1 row per thread, full 64 words
  {
    const uint32_t* src =
        (const uint32_t*)(Q + (qb * 128 + tid) * C_MODEL + h * DHEAD);
#pragma unroll
    for (int i = 0; i < 16; i++) {
      uint4 v4 = *(const uint4*)(src + i * 4);
      uint32_t* d = &Ps[tid * KS_W + i * 4];
      d[0] = v4.x; d[1] = v4.y; d[2] = v4.z; d[3] = v4.w;
    }
  }
  __syncthreads();

  uint32_t qf[2][8][4];
#pragma unroll
  for (int t = 0; t < 2; t++) {
    const int m0 = w * 32 + t * 16;
#pragma unroll
    for (int kk = 0; kk < 8; kk++) {
      qf[t][kk][0] = Ps[(m0 + l4) * KS_W + kk * 8 + lm4];
      qf[t][kk][1] = Ps[(m0 + l4 + 8) * KS_W + kk * 8 + lm4];
      qf[t][kk][2] = Ps[(m0 + l4) * KS_W + kk * 8 + lm4 + 4];
      qf[t][kk][3] = Ps[(m0 + l4 + 8) * KS_W + kk * 8 + lm4 + 4];
    }
  }

  float m_i[2][2], l_i[2][2];
  float oacc[2][8][4];
#pragma unroll
  for (int t = 0; t < 2; t++)
#pragma unroll
    for (int rh = 0; rh < 2; rh++) { m_i[t][rh] = -1e30f; l_i[t][rh] = 0.f; }
#pragma unroll
  for (int t = 0; t < 2; t++)
#pragma unroll
    for (int j = 0; j < 8; j++)
#pragma unroll
      for (int c = 0; c < 4; c++) oacc[t][j][c] = 0.f;

  float sc[2][8][4];  // scores: softmaxed one iteration later

  CP_WAIT0();
  __syncthreads();
  {
    const uint32_t* Ks = smu + SM_KS;
#pragma unroll
    for (int t = 0; t < 2; t++)
#pragma unroll
      for (int j = 0; j < 8; j++)
#pragma unroll
        for (int c = 0; c < 4; c++) sc[t][j][c] = 0.f;
#pragma unroll
    for (int kk = 0; kk < 8; kk++) {
#pragma unroll
      for (int j = 0; j < 8; j++) {
        uint32_t bf[2];
        bf[0] = Ks[(j * 8 + l4) * KS_W + kk * 8 + lm4];
        bf[1] = Ks[(j * 8 + l4) * KS_W + kk * 8 + lm4 + 4];
        mma_tf32(sc[0][j], qf[0][kk], bf);
        mma_tf32(sc[1][j], qf[1][kk], bf);
      }
    }
  }

  for (int kt = 0; kt < nkt; kt++) {
    const bool active = (kt * 64 <= wrow_last);

    if (kt + 1 < nkt) ASTAGE(kt + 1, (kt + 1) & 1);

    if (active) {
      if (kt >= 2 * qb) {
#pragma unroll
        for (int t = 0; t < 2; t++) {
          const int r0 = qb * 128 + w * 32 + t * 16 + l4;
#pragma unroll
          for (int j = 0; j < 8; j++) {
            const int c0 = kt * 64 + j * 8 + 2 * lm4;
            sc[t][j][0] = (c0 > r0) ? -1e30f : sc[t][j][0] * scale2;
            sc[t][j][1] = (c0 + 1 > r0) ? -1e30f : sc[t][j][1] * scale2;
            sc[t][j][2] = (c0 > r0 + 8) ? -1e30f : sc[t][j][2] * scale2;
            sc[t][j][3] = (c0 + 1 > r0 + 8) ? -1e30f : sc[t][j][3] * scale2;
          }
        }
      } else {
#pragma unroll
        for (int t = 0; t < 2; t++)
#pragma unroll
          for (int j = 0; j < 8; j++)
#pragma unroll
            for (int c = 0; c < 4; c++) sc[t][j][c] *= scale2;
      }

#pragma unroll
      for (int t = 0; t < 2; t++) {
#pragma unroll
        for (int rh = 0; rh < 2; rh++) {
          const int cb = rh * 2;
          float rm = sc[t][0][cb];
#pragma unroll
          for (int j = 0; j < 8; j++)
            rm = fmaxf(rm, fmaxf(sc[t][j][cb], sc[t][j][cb + 1]));
          rm = fmaxf(rm, __shfl_xor_sync(0xffffffffu, rm, 1));
          rm = fmaxf(rm, __shfl_xor_sync(0xffffffffu, rm, 2));
          const float mnew = fmaxf(m_i[t][rh], rm);
          const float alpha = exp2f(m_i[t][rh] - mnew);
          float rs = 0.f;
#pragma unroll
          for (int j = 0; j < 8; j++) {
            const float p0 = exp2f(sc[t][j][cb] - mnew);
            const float p1 = exp2f(sc[t][j][cb + 1] - mnew);
            sc[t][j][cb] = p0; sc[t][j][cb + 1] = p1;
            rs += p0 + p1;
          }
          rs += __shfl_xor_sync(0xffffffffu, rs, 1);
          rs += __shfl_xor_sync(0xffffffffu, rs, 2);
          l_i[t][rh] = l_i[t][rh] * alpha + rs;
          m_i[t][rh] = mnew;
#pragma unroll
          for (int j = 0; j < 8; j++) {
            oacc[t][j][cb] *= alpha;
            oacc[t][j][cb + 1] *= alpha;
          }
          const int pr = (w * 32 + t * 16 + l4 + rh * 8) * KS_W + 2 * lm4;
#pragma unroll
          for (int j = 0; j < 8; j++) {
            uint2 pp =
                make_uint2(f2tf32(sc[t][j][cb]), f2tf32(sc[t][j][cb + 1]));
            *(uint2*)&Ps[pr + j * 8] = pp;
          }
        }
      }
      __syncwarp();

      const uint32_t* Vs = smu + SM_VS + (kt & 1) * 64 * VS_W;
#pragma unroll
      for (int kk = 0; kk < 8; kk++) {
        uint32_t af0[4], af1[4];
        af0[0] = Ps[(w * 32 + l4) * KS_W + kk * 8 + lm4];
        af0[1] = Ps[(w * 32 + l4 + 8) * KS_W + kk * 8 + lm4];
        af0[2] = Ps[(w * 32 + l4) * KS_W + kk * 8 + lm4 + 4];
        af0[3] = Ps[(w * 32 + l4 + 8) * KS_W + kk * 8 + lm4 + 4];
        af1[0] = Ps[(w * 32 + 16 + l4) * KS_W + kk * 8 + lm4];
        af1[1] = Ps[(w * 32 + 24 + l4) * KS_W + kk * 8 + lm4];
        af1[2] = Ps[(w * 32 + 16 + l4) * KS_W + kk * 8 + lm4 + 4];
        af1[3] = Ps[(w * 32 + 24 + l4) * KS_W + kk * 8 + lm4 + 4];
#pragma unroll
        for (int j = 0; j < 8; j++) {
          uint32_t bf[2];
          bf[0] = Vs[(kk * 8 + lm4) * VS_W + j * 8 + l4];
          bf[1] = Vs[(kk * 8 + lm4 + 4) * VS_W + j * 8 + l4];
          mma_tf32(oacc[0][j], af0, bf);
          mma_tf32(oacc[1][j], af1, bf);
        }
      }
      __syncwarp();
    }

    CP_WAIT0();
    __syncthreads();

    if (kt + 1 < nkt && (kt + 1) * 64 <= wrow_last) {
      const uint32_t* Ks = smu + SM_KS + ((kt + 1) & 1) * 64 * KS_W;
#pragma unroll
      for (int t = 0; t < 2; t++)
#pragma unroll
        for (int j = 0; j < 8; j++)
#pragma unroll
          for (int c = 0; c < 4; c++) sc[t][j][c] = 0.f;
#pragma unroll
      for (int kk = 0; kk < 8; kk++) {
#pragma unroll
        for (int j = 0; j < 8; j++) {
          uint32_t bf[2];
          bf[0] = Ks[(j * 8 + l4) * KS_W + kk * 8 + lm4];
          bf[1] = Ks[(j * 8 + l4) * KS_W + kk * 8 + lm4 + 4];
          mma_tf32(sc[0][j], qf[0][kk], bf);
          mma_tf32(sc[1][j], qf[1][kk], bf);
        }
      }
    }
  }

  // epilogue: normalize, tf32-round (consumed raw by gemm_out), store
#pragma unroll
  for (int t = 0; t < 2; t++) {
#pragma unroll
    for (int rh = 0; rh < 2; rh++) {
      const float inv = 1.f / l_i[t][rh];
      const int r = qb * 128 + w * 32 + t * 16 + l4 + rh * 8;
      float* dst = O + r * C_MODEL + h * DHEAD + 2 * lm4;
#pragma unroll
      for (int j = 0; j < 8; j++) {
        float o0 = __uint_as_float(f2tf32(oacc[t][j][rh * 2] * inv));
        float o1 = __uint_as_float(f2tf32(oacc[t][j][rh * 2 + 1] * inv));
        *(float2*)(dst + j * 8) = make_float2(o0, o1);
      }
    }
  }
#undef ASTAGE
}

// ---------------------------------------------------------------------------
extern "C" void kernel_launch(void* const* d_in, const int* in_sizes, int n_in,
                              void* d_out, int out_size) {
  const float* x  = (const float*)d_in[0];
  const float* Wq = (const float*)d_in[1];
  const float* bq = (const float*)d_in[2];
  const float* Wk = (const float*)d_in[3];
  const float* bk = (const float*)d_in[4];
  const float* Wv = (const float*)d_in[5];
  const float* bv = (const float*)d_in[6];
  const float* Wo = (const float*)d_in[7];
  const float* bo = (const float*)d_in[8];
  float* out = (float*)d_out;

  float *qp, *kp, *vp, *ap, *xr, *wqr, *wkr, *wvr, *wor;
  cudaGetSymbolAddress((void**)&qp, g_q);
  cudaGetSymbolAddress((void**)&kp, g_k);
  cudaGetSymbolAddress((void**)&vp, g_v);
  cudaGetSymbolAddress((void**)&ap, g_attn);
  cudaGetSymbolAddress((void**)&xr, g_xr);
  cudaGetSymbolAddress((void**)&wqr, g_wqr);
  cudaGetSymbolAddress((void**)&wkr, g_wkr);
  cudaGetSymbolAddress((void**)&wvr, g_wvr);
  cudaGetSymbolAddress((void**)&wor, g_wor);

  cudaFuncSetAttribute(gemm_qkv, cudaFuncAttributeMaxDynamicSharedMemorySize,
                       GEMM_SMEM);
  cudaFuncSetAttribute(gemm_out, cudaFuncAttributeMaxDynamicSharedMemorySize,
                       GEMM_SMEM);
  cudaFuncSetAttribute(flash_attn_tc,
                       cudaFuncAttributeMaxDynamicSharedMemorySize,
                       (int)ATTN_SMEM);

  // pre-pass: tf32-round x and weights
  dim3 gr(T_SEQ * C_MODEL / (256 * 4), 5);  // (4096, 5)
  round_pass<<<gr, 256>>>(x, Wq, Wk, Wv, Wo, xr, wqr, wkr, wvr, wor);

  dim3 gqkv(C_MODEL / 128, T_SEQ / 128, 3);  // (8, 32, 3)
  gemm_qkv<<<gqkv, 128, GEMM_SMEM>>>(xr, wqr, bq, qp, wkr, bk, kp, wvr, bv,
                                     vp);

  dim3 ga(T_SEQ / 128, NHEADS);              // (32, 16)
  flash_attn_tc<<<ga, 128, ATTN_SMEM>>>(qp, kp, vp, ap);

  dim3 gb(C_MODEL / 128, T_SEQ / 128);       // (8, 32)
  gemm_out<<<gb, 128, GEMM_SMEM>>>(ap, wor, bo, out);
}